// round 1
// baseline (speedup 1.0000x reference)
#include <cuda_runtime.h>
#include <math.h>
#include <stdint.h>

#define Tn   512
#define Bn   64
#define OBSn 512
#define Hn   1024
#define An   18
#define G4n  4096
#define Mn   32768   // Tn*Bn

// ---------------- scratch (device globals; no runtime allocation) ----------------
__device__ float g_enc[(size_t)Mn * Hn];        // encoded [m][h]            (128 MB)
__device__ float g_xg [(size_t)Tn * G4n * Bn];  // x_gates transposed [t][g][b] (512 MB)
__device__ float g_lat[(size_t)Tn * Hn * Bn];   // latent transposed  [t][h][b] (128 MB)
__device__ unsigned g_bar_count;
__device__ unsigned g_bar_gen;

// =====================================================================
// SGEMM: C[m][n] = A[m][:K] . Bm[n][:K] (+bias1 (+bias2)) (opt relu)
// A row-major [M,K], Bm row-major [N,K]. BM=BN=128, BK=16, 256 thr, 8x8.
// XGST mode stores transposed into g_xg as [t][n][b], m = t*64+b.
// =====================================================================
template<bool RELU, bool XGST, bool HASB2>
__global__ void __launch_bounds__(256, 2) sgemm_bt(
    const float* __restrict__ A, const float* __restrict__ Bm,
    const float* __restrict__ bias1, const float* __restrict__ bias2,
    float* __restrict__ C, int K, int N)
{
    __shared__ float As[16][132];
    __shared__ float Bs[16][132];
    const int bm = blockIdx.y << 7;
    const int bn = blockIdx.x << 7;
    const int tid = threadIdx.x;
    const int tr = (tid >> 4) << 3;   // 0..120 step 8
    const int tc = (tid & 15) << 3;   // 0..120 step 8
    const int lr = tid >> 2;          // 0..63
    const int lk = (tid & 3) << 2;    // 0,4,8,12

    const float* Ap = A  + (size_t)(bm + lr) * K + lk;
    const float* Bp = Bm + (size_t)(bn + lr) * K + lk;
    float4 a0 = *(const float4*)(Ap);
    float4 a1 = *(const float4*)(Ap + (size_t)64 * K);
    float4 b0 = *(const float4*)(Bp);
    float4 b1 = *(const float4*)(Bp + (size_t)64 * K);

    float acc[8][8];
#pragma unroll
    for (int i = 0; i < 8; i++)
#pragma unroll
        for (int j = 0; j < 8; j++) acc[i][j] = 0.f;

    for (int k0 = 0; k0 < K; k0 += 16) {
        As[lk+0][lr]    = a0.x; As[lk+1][lr]    = a0.y; As[lk+2][lr]    = a0.z; As[lk+3][lr]    = a0.w;
        As[lk+0][lr+64] = a1.x; As[lk+1][lr+64] = a1.y; As[lk+2][lr+64] = a1.z; As[lk+3][lr+64] = a1.w;
        Bs[lk+0][lr]    = b0.x; Bs[lk+1][lr]    = b0.y; Bs[lk+2][lr]    = b0.z; Bs[lk+3][lr]    = b0.w;
        Bs[lk+0][lr+64] = b1.x; Bs[lk+1][lr+64] = b1.y; Bs[lk+2][lr+64] = b1.z; Bs[lk+3][lr+64] = b1.w;
        __syncthreads();
        if (k0 + 16 < K) {
            a0 = *(const float4*)(Ap + k0 + 16);
            a1 = *(const float4*)(Ap + (size_t)64 * K + k0 + 16);
            b0 = *(const float4*)(Bp + k0 + 16);
            b1 = *(const float4*)(Bp + (size_t)64 * K + k0 + 16);
        }
#pragma unroll
        for (int kk = 0; kk < 16; kk++) {
            float av[8], bv[8];
            *(float4*)(av)     = *(const float4*)(&As[kk][tr]);
            *(float4*)(av + 4) = *(const float4*)(&As[kk][tr + 4]);
            *(float4*)(bv)     = *(const float4*)(&Bs[kk][tc]);
            *(float4*)(bv + 4) = *(const float4*)(&Bs[kk][tc + 4]);
#pragma unroll
            for (int i = 0; i < 8; i++)
#pragma unroll
                for (int j = 0; j < 8; j++)
                    acc[i][j] = fmaf(av[i], bv[j], acc[i][j]);
        }
        __syncthreads();
    }

#pragma unroll
    for (int i = 0; i < 8; i++) {
        const int m = bm + tr + i;
#pragma unroll
        for (int j = 0; j < 8; j++) {
            const int n = bn + tc + j;
            float v = acc[i][j] + bias1[n];
            if (HASB2) v += bias2[n];
            if (RELU)  v = fmaxf(v, 0.f);
            if (XGST) {
                const int t = m >> 6, b = m & 63;
                g_xg[((size_t)t * G4n + n) * Bn + b] = v;
            } else {
                C[(size_t)m * N + n] = v;
            }
        }
    }
}

// =====================================================================
// Persistent LSTM scan. 128 blocks x 256 threads, 1 block/SM.
// Block owns 8 hidden units j0..j0+7 -> 32 gate rows of W_hh kept in smem
// (k-major [1024][32], 128KB). 8 warps = 8 K-slices of 128 (split-K),
// per-thread 8x8 outer product; partials reduced through smem (64KB).
// h is carried in g_lat[t][h][b] (masked h == carried h in the reference).
// =====================================================================
__device__ __forceinline__ float sigf(float x) { return 1.f / (1.f + __expf(-x)); }

__global__ void __launch_bounds__(256, 1) lstm_kernel(
    const float* __restrict__ W_hh, const float* __restrict__ mask,
    float* __restrict__ out_h, float* __restrict__ out_c, int nblk)
{
    extern __shared__ float sm[];
    float* Ws  = sm;                 // [1024][32] k-major
    float* red = sm + 1024 * 32;     // [8][32][64]
    const int tid = threadIdx.x;
    const int j0 = blockIdx.x << 3;

    // Stage this block's 32 W_hh rows, transposed to k-major.
    for (int i = tid; i < 32 * 256; i += 256) {
        const int r  = i >> 8;             // 0..31  (= q*8 + jj)
        const int kq = (i & 255) << 2;     // 0..1020 step 4
        const int grow = ((r >> 3) << 10) + j0 + (r & 7);   // q*1024 + j0 + jj
        const float4 w = *(const float4*)(W_hh + (size_t)grow * Hn + kq);
        Ws[(kq + 0) * 32 + r] = w.x;
        Ws[(kq + 1) * 32 + r] = w.y;
        Ws[(kq + 2) * 32 + r] = w.z;
        Ws[(kq + 3) * 32 + r] = w.w;
    }

    const int wid = tid >> 5;
    const int t32 = tid & 31;
    const int rg  = (t32 >> 3) << 3;   // row base 0,8,16,24
    const int bg  = (t32 & 7) << 3;    // batch base 0..56
    float c0r = 0.f, c1r = 0.f;        // cell state for pairs (tid) and (tid+256)

    unsigned gen = 0;
    if (tid == 0) gen = *(volatile unsigned*)&g_bar_gen;
    __syncthreads();                   // Ws ready; gen sampled before any arrival

    for (int t = 0; t < Tn; t++) {
        float acc[8][8];
#pragma unroll
        for (int i = 0; i < 8; i++)
#pragma unroll
            for (int j = 0; j < 8; j++) acc[i][j] = 0.f;

        if (t > 0) {
            const float* Hrow = g_lat + (size_t)(t - 1) * (Hn * Bn);
            const int kend = (wid << 7) + 128;
#pragma unroll 2
            for (int k = wid << 7; k < kend; k++) {
                const float* wp = Ws + k * 32 + rg;
                const float4 wa = *(const float4*)(wp);
                const float4 wb = *(const float4*)(wp + 4);
                const float* hp = Hrow + (k << 6) + bg;
                const float4 ha = __ldcg((const float4*)(hp));
                const float4 hb = __ldcg((const float4*)(hp + 4));
                const float av[8] = {wa.x, wa.y, wa.z, wa.w, wb.x, wb.y, wb.z, wb.w};
                const float hv[8] = {ha.x, ha.y, ha.z, ha.w, hb.x, hb.y, hb.z, hb.w};
#pragma unroll
                for (int i = 0; i < 8; i++)
#pragma unroll
                    for (int j = 0; j < 8; j++)
                        acc[i][j] = fmaf(av[i], hv[j], acc[i][j]);
            }
        }

        // publish split-K partials
#pragma unroll
        for (int i = 0; i < 8; i++)
#pragma unroll
            for (int j = 0; j < 8; j++)
                red[((wid << 5) + rg + i) * 64 + bg + j] = acc[i][j];
        __syncthreads();

        // reduce + activations: 512 (jj,b) pairs -> 2 per thread
#pragma unroll
        for (int pp = 0; pp < 2; pp++) {
            const int p  = tid + (pp << 8);
            const int jj = p >> 6;
            const int b  = p & 63;
            float gate[4];
#pragma unroll
            for (int q = 0; q < 4; q++) {
                const int r = (q << 3) + jj;
                float s = g_xg[((size_t)t * G4n + (q << 10) + j0 + jj) * Bn + b];
#pragma unroll
                for (int ww = 0; ww < 8; ww++)
                    s += red[((ww << 5) + r) * 64 + b];
                gate[q] = s;
            }
            const float cprev = pp ? c1r : c0r;
            float cn = sigf(gate[1]) * cprev + sigf(gate[0]) * tanhf(gate[2]);
            float hn = sigf(gate[3]) * tanhf(cn);
            const float m = mask[t * Bn + b];
            hn *= m; cn *= m;
            if (pp) c1r = cn; else c0r = cn;
            g_lat[(size_t)t * (Hn * Bn) + ((size_t)(j0 + jj) << 6) + b] = hn;
            if (t == Tn - 1) {
                out_h[b * Hn + j0 + jj] = hn;
                out_c[b * Hn + j0 + jj] = cn;
            }
        }

        // ---- grid barrier (sense-reversing generation counter) ----
        __threadfence();
        __syncthreads();
        if (tid == 0) {
            const unsigned arr = atomicAdd(&g_bar_count, 1);
            if (arr == (unsigned)(nblk - 1)) {
                atomicExch(&g_bar_count, 0);
                __threadfence();
                atomicAdd(&g_bar_gen, 1);
            } else {
                while (*(volatile unsigned*)&g_bar_gen == gen) { }
            }
            gen++;
            __threadfence();
        }
        __syncthreads();
    }
}

// =====================================================================
// Decoder: values[t][b][a] = (sum_h lat[t][h][b]*W_dec[a][h] + b_dec[a]) * mask[t][b]
// One block per t. W_dec staged in smem; split-K over 4 h-slices.
// =====================================================================
__global__ void __launch_bounds__(256, 1) decoder_kernel(
    const float* __restrict__ Wd, const float* __restrict__ bd,
    const float* __restrict__ mask, float* __restrict__ out_values)
{
    extern __shared__ float dsm[];
    float* Wds  = dsm;               // [18][1024]
    float* red2 = dsm + 18 * 1024;   // [4][64][18]
    const int t = blockIdx.x;
    const int tid = threadIdx.x;

    for (int i = tid; i < (18 * 1024) / 4; i += 256)
        ((float4*)Wds)[i] = ((const float4*)Wd)[i];
    __syncthreads();

    const int s = tid >> 6;   // h-slice 0..3
    const int b = tid & 63;
    float acc[18];
#pragma unroll
    for (int a = 0; a < 18; a++) acc[a] = 0.f;

    const float* L = g_lat + (size_t)t * (Hn * Bn);
    const int hend = (s + 1) << 8;
    for (int h = s << 8; h < hend; h++) {
        const float x = __ldcg(L + (h << 6) + b);
#pragma unroll
        for (int a = 0; a < 18; a++)
            acc[a] = fmaf(x, Wds[a * 1024 + h], acc[a]);
    }
#pragma unroll
    for (int a = 0; a < 18; a++) red2[(s * 64 + b) * 18 + a] = acc[a];
    __syncthreads();

    for (int o = tid; o < 64 * 18; o += 256) {
        const int b2 = o / 18;
        const int a  = o - b2 * 18;
        float v = red2[b2 * 18 + a] + red2[(64 + b2) * 18 + a]
                + red2[(128 + b2) * 18 + a] + red2[(192 + b2) * 18 + a];
        v = (v + bd[a]) * mask[t * Bn + b2];
        out_values[(size_t)t * (Bn * An) + o] = v;
    }
}

// =====================================================================
extern "C" void kernel_launch(void* const* d_in, const int* in_sizes, int n_in,
                              void* d_out, int out_size)
{
    const float* obs   = (const float*)d_in[0];
    const float* mask  = (const float*)d_in[1];
    const float* W_enc = (const float*)d_in[2];
    const float* b_enc = (const float*)d_in[3];
    const float* W_ih  = (const float*)d_in[4];
    const float* b_ih  = (const float*)d_in[5];
    const float* W_hh  = (const float*)d_in[6];
    const float* b_hh  = (const float*)d_in[7];
    const float* W_dec = (const float*)d_in[8];
    const float* b_dec = (const float*)d_in[9];

    float* out        = (float*)d_out;
    float* out_values = out;                                   // [512][64][18]
    float* out_h      = out + (size_t)Tn * Bn * An;            // [64][1024]
    float* out_c      = out_h + (size_t)Bn * Hn;               // [64][1024]

    float* enc_ptr = nullptr;
    cudaGetSymbolAddress((void**)&enc_ptr, g_enc);

    cudaFuncSetAttribute(lstm_kernel,    cudaFuncAttributeMaxDynamicSharedMemorySize, 196608);
    cudaFuncSetAttribute(decoder_kernel, cudaFuncAttributeMaxDynamicSharedMemorySize, 92160);

    // 1) encoded = relu(obs @ W_enc^T + b_enc)          [32768,1024]
    dim3 g1(Hn / 128, Mn / 128);
    sgemm_bt<true, false, false><<<g1, 256>>>(obs, W_enc, b_enc, nullptr, enc_ptr, OBSn, Hn);

    // 2) x_gates = enc @ W_ih^T + b_ih + b_hh  -> g_xg [t][g][b]
    dim3 g2(G4n / 128, Mn / 128);
    sgemm_bt<false, true, true><<<g2, 256>>>(enc_ptr, W_ih, b_ih, b_hh, nullptr, Hn, G4n);

    // 3) persistent LSTM scan -> g_lat [t][h][b], out_h, out_c
    lstm_kernel<<<128, 256, 196608>>>(W_hh, mask, out_h, out_c, 128);

    // 4) decoder -> out_values
    decoder_kernel<<<Tn, 256, 92160>>>(W_dec, b_dec, mask, out_values);
}

// round 4
// speedup vs baseline: 1.2933x; 1.2933x over previous
#include <cuda_runtime.h>
#include <math.h>
#include <stdint.h>

#define Tn   512
#define Bn   64
#define OBSn 512
#define Hn   1024
#define An   18
#define G4n  4096
#define Mn   32768   // Tn*Bn

// ---------------- scratch (device globals; no runtime allocation) ----------------
__device__ float g_enc[(size_t)Mn * Hn];        // encoded [m][h]            (128 MB)
__device__ float g_xg [(size_t)Tn * G4n * Bn];  // x_gates transposed [t][g][b] (512 MB)
__device__ float g_lat[(size_t)Tn * Hn * Bn];   // latent transposed  [t][h][b] (128 MB)
__device__ unsigned g_bar_count;
__device__ unsigned g_bar_gen;

__device__ __forceinline__ unsigned f2tf32(float x) {
    unsigned r;
    asm("cvt.rna.tf32.f32 %0, %1;" : "=r"(r) : "f"(x));
    return r;
}

// =====================================================================
// TF32 tensor-core GEMM: C[m][n] = A[m][:K] . Bm[n][:K] (+bias) (opt relu)
// A row-major [M,K], Bm row-major [N,K]. Block tile 128x128, BK=16,
// 256 thr = 8 warps (4x2), warp tile 32x64, mma.sync.m16n8k8 tf32.
// XGST mode stores transposed into g_xg as [t][n][b], m = t*64+b.
// =====================================================================
template<bool RELU, bool XGST, bool HASB2>
__global__ void __launch_bounds__(256, 2) tf32_gemm(
    const float* __restrict__ A, const float* __restrict__ Bm,
    const float* __restrict__ bias1, const float* __restrict__ bias2,
    float* __restrict__ C, int K, int N)
{
    __shared__ unsigned As[128][20];   // [m][k] pad-20 => conflict-free frag LDS
    __shared__ unsigned Bs[128][20];   // [n][k]
    const int tid  = threadIdx.x;
    const int wid  = tid >> 5, lane = tid & 31;
    const int wr   = wid >> 1, wc = wid & 1;       // warp grid 4x2
    const int gq   = lane >> 2, tg = lane & 3;     // mma group / in-group id
    const int bm   = blockIdx.y << 7;
    const int bn   = blockIdx.x << 7;
    const int lr   = tid >> 2;                     // 0..63
    const int lk   = (tid & 3) << 2;               // 0,4,8,12

    const float* Ap = A  + (size_t)(bm + lr) * K + lk;
    const float* Bp = Bm + (size_t)(bn + lr) * K + lk;
    float4 pa0 = *(const float4*)(Ap);
    float4 pa1 = *(const float4*)(Ap + (size_t)64 * K);
    float4 pb0 = *(const float4*)(Bp);
    float4 pb1 = *(const float4*)(Bp + (size_t)64 * K);

    float acc[16][4];
#pragma unroll
    for (int t = 0; t < 16; t++)
#pragma unroll
        for (int e = 0; e < 4; e++) acc[t][e] = 0.f;

    for (int k0 = 0; k0 < K; k0 += 16) {
        uint4 u;
        u.x = f2tf32(pa0.x); u.y = f2tf32(pa0.y); u.z = f2tf32(pa0.z); u.w = f2tf32(pa0.w);
        *(uint4*)&As[lr][lk] = u;
        u.x = f2tf32(pa1.x); u.y = f2tf32(pa1.y); u.z = f2tf32(pa1.z); u.w = f2tf32(pa1.w);
        *(uint4*)&As[lr + 64][lk] = u;
        u.x = f2tf32(pb0.x); u.y = f2tf32(pb0.y); u.z = f2tf32(pb0.z); u.w = f2tf32(pb0.w);
        *(uint4*)&Bs[lr][lk] = u;
        u.x = f2tf32(pb1.x); u.y = f2tf32(pb1.y); u.z = f2tf32(pb1.z); u.w = f2tf32(pb1.w);
        *(uint4*)&Bs[lr + 64][lk] = u;
        __syncthreads();

        if (k0 + 16 < K) {
            pa0 = *(const float4*)(Ap + k0 + 16);
            pa1 = *(const float4*)(Ap + (size_t)64 * K + k0 + 16);
            pb0 = *(const float4*)(Bp + k0 + 16);
            pb1 = *(const float4*)(Bp + (size_t)64 * K + k0 + 16);
        }

#pragma unroll
        for (int ks = 0; ks < 2; ks++) {
            const int kf = ks << 3;
            unsigned af[2][4], bf[8][2];
#pragma unroll
            for (int i = 0; i < 2; i++) {
                const int mr = (wr << 5) + (i << 4) + gq;
                af[i][0] = As[mr][kf + tg];
                af[i][1] = As[mr + 8][kf + tg];
                af[i][2] = As[mr][kf + tg + 4];
                af[i][3] = As[mr + 8][kf + tg + 4];
            }
#pragma unroll
            for (int j = 0; j < 8; j++) {
                const int nn = (wc << 6) + (j << 3) + gq;
                bf[j][0] = Bs[nn][kf + tg];
                bf[j][1] = Bs[nn][kf + tg + 4];
            }
#pragma unroll
            for (int i = 0; i < 2; i++)
#pragma unroll
                for (int j = 0; j < 8; j++) {
                    float* c = acc[i * 8 + j];
                    asm volatile(
                        "mma.sync.aligned.m16n8k8.row.col.f32.tf32.tf32.f32 "
                        "{%0,%1,%2,%3}, {%4,%5,%6,%7}, {%8,%9}, {%0,%1,%2,%3};"
                        : "+f"(c[0]), "+f"(c[1]), "+f"(c[2]), "+f"(c[3])
                        : "r"(af[i][0]), "r"(af[i][1]), "r"(af[i][2]), "r"(af[i][3]),
                          "r"(bf[j][0]), "r"(bf[j][1]));
                }
        }
        __syncthreads();
    }

    // ---- epilogue ----
#pragma unroll
    for (int i = 0; i < 2; i++) {
#pragma unroll
        for (int j = 0; j < 8; j++) {
            const int r0 = bm + (wr << 5) + (i << 4) + gq;
            const int cb = bn + (wc << 6) + (j << 3) + (tg << 1);
            float bv0 = bias1[cb]     + (HASB2 ? bias2[cb]     : 0.f);
            float bv1 = bias1[cb + 1] + (HASB2 ? bias2[cb + 1] : 0.f);
            const float* c = acc[i * 8 + j];
            float v00 = c[0] + bv0, v01 = c[1] + bv1;   // row r0
            float v10 = c[2] + bv0, v11 = c[3] + bv1;   // row r0+8
            if (RELU) {
                v00 = fmaxf(v00, 0.f); v01 = fmaxf(v01, 0.f);
                v10 = fmaxf(v10, 0.f); v11 = fmaxf(v11, 0.f);
            }
            if (XGST) {
                const int t0 = r0 >> 6, b0 = r0 & 63;
                const int t1 = (r0 + 8) >> 6, b1 = (r0 + 8) & 63;
                g_xg[((size_t)t0 * G4n + cb)     * Bn + b0] = v00;
                g_xg[((size_t)t0 * G4n + cb + 1) * Bn + b0] = v01;
                g_xg[((size_t)t1 * G4n + cb)     * Bn + b1] = v10;
                g_xg[((size_t)t1 * G4n + cb + 1) * Bn + b1] = v11;
            } else {
                *(float2*)(C + (size_t)r0 * N + cb)       = make_float2(v00, v01);
                *(float2*)(C + (size_t)(r0 + 8) * N + cb) = make_float2(v10, v11);
            }
        }
    }
}

// =====================================================================
// Persistent LSTM scan (unchanged from R1 — FFMA-roofline-bound; tensor
// conversion is next). 128 blocks x 256 threads, 1 block/SM.
// =====================================================================
__device__ __forceinline__ float sigf(float x) { return 1.f / (1.f + __expf(-x)); }

__global__ void __launch_bounds__(256, 1) lstm_kernel(
    const float* __restrict__ W_hh, const float* __restrict__ mask,
    float* __restrict__ out_h, float* __restrict__ out_c, int nblk)
{
    extern __shared__ float sm[];
    float* Ws  = sm;                 // [1024][32] k-major
    float* red = sm + 1024 * 32;     // [8][32][64]
    const int tid = threadIdx.x;
    const int j0 = blockIdx.x << 3;

    for (int i = tid; i < 32 * 256; i += 256) {
        const int r  = i >> 8;
        const int kq = (i & 255) << 2;
        const int grow = ((r >> 3) << 10) + j0 + (r & 7);
        const float4 w = *(const float4*)(W_hh + (size_t)grow * Hn + kq);
        Ws[(kq + 0) * 32 + r] = w.x;
        Ws[(kq + 1) * 32 + r] = w.y;
        Ws[(kq + 2) * 32 + r] = w.z;
        Ws[(kq + 3) * 32 + r] = w.w;
    }

    const int wid = tid >> 5;
    const int t32 = tid & 31;
    const int rg  = (t32 >> 3) << 3;
    const int bg  = (t32 & 7) << 3;
    float c0r = 0.f, c1r = 0.f;

    unsigned gen = 0;
    if (tid == 0) gen = *(volatile unsigned*)&g_bar_gen;
    __syncthreads();

    for (int t = 0; t < Tn; t++) {
        float acc[8][8];
#pragma unroll
        for (int i = 0; i < 8; i++)
#pragma unroll
            for (int j = 0; j < 8; j++) acc[i][j] = 0.f;

        if (t > 0) {
            const float* Hrow = g_lat + (size_t)(t - 1) * (Hn * Bn);
            const int kend = (wid << 7) + 128;
#pragma unroll 2
            for (int k = wid << 7; k < kend; k++) {
                const float* wp = Ws + k * 32 + rg;
                const float4 wa = *(const float4*)(wp);
                const float4 wb = *(const float4*)(wp + 4);
                const float* hp = Hrow + (k << 6) + bg;
                const float4 ha = __ldcg((const float4*)(hp));
                const float4 hb = __ldcg((const float4*)(hp + 4));
                const float av[8] = {wa.x, wa.y, wa.z, wa.w, wb.x, wb.y, wb.z, wb.w};
                const float hv[8] = {ha.x, ha.y, ha.z, ha.w, hb.x, hb.y, hb.z, hb.w};
#pragma unroll
                for (int i = 0; i < 8; i++)
#pragma unroll
                    for (int j = 0; j < 8; j++)
                        acc[i][j] = fmaf(av[i], hv[j], acc[i][j]);
            }
        }

#pragma unroll
        for (int i = 0; i < 8; i++)
#pragma unroll
            for (int j = 0; j < 8; j++)
                red[((wid << 5) + rg + i) * 64 + bg + j] = acc[i][j];
        __syncthreads();

#pragma unroll
        for (int pp = 0; pp < 2; pp++) {
            const int p  = tid + (pp << 8);
            const int jj = p >> 6;
            const int b  = p & 63;
            float gate[4];
#pragma unroll
            for (int q = 0; q < 4; q++) {
                const int r = (q << 3) + jj;
                float s = g_xg[((size_t)t * G4n + (q << 10) + j0 + jj) * Bn + b];
#pragma unroll
                for (int ww = 0; ww < 8; ww++)
                    s += red[((ww << 5) + r) * 64 + b];
                gate[q] = s;
            }
            const float cprev = pp ? c1r : c0r;
            float cn = sigf(gate[1]) * cprev + sigf(gate[0]) * tanhf(gate[2]);
            float hn = sigf(gate[3]) * tanhf(cn);
            const float m = mask[t * Bn + b];
            hn *= m; cn *= m;
            if (pp) c1r = cn; else c0r = cn;
            g_lat[(size_t)t * (Hn * Bn) + ((size_t)(j0 + jj) << 6) + b] = hn;
            if (t == Tn - 1) {
                out_h[b * Hn + j0 + jj] = hn;
                out_c[b * Hn + j0 + jj] = cn;
            }
        }

        __threadfence();
        __syncthreads();
        if (tid == 0) {
            const unsigned arr = atomicAdd(&g_bar_count, 1);
            if (arr == (unsigned)(nblk - 1)) {
                atomicExch(&g_bar_count, 0);
                __threadfence();
                atomicAdd(&g_bar_gen, 1);
            } else {
                while (*(volatile unsigned*)&g_bar_gen == gen) { }
            }
            gen++;
            __threadfence();
        }
        __syncthreads();
    }
}

// =====================================================================
// Decoder (unchanged)
// =====================================================================
__global__ void __launch_bounds__(256, 1) decoder_kernel(
    const float* __restrict__ Wd, const float* __restrict__ bd,
    const float* __restrict__ mask, float* __restrict__ out_values)
{
    extern __shared__ float dsm[];
    float* Wds  = dsm;               // [18][1024]
    float* red2 = dsm + 18 * 1024;   // [4][64][18]
    const int t = blockIdx.x;
    const int tid = threadIdx.x;

    for (int i = tid; i < (18 * 1024) / 4; i += 256)
        ((float4*)Wds)[i] = ((const float4*)Wd)[i];
    __syncthreads();

    const int s = tid >> 6;
    const int b = tid & 63;
    float acc[18];
#pragma unroll
    for (int a = 0; a < 18; a++) acc[a] = 0.f;

    const float* L = g_lat + (size_t)t * (Hn * Bn);
    const int hend = (s + 1) << 8;
    for (int h = s << 8; h < hend; h++) {
        const float x = __ldcg(L + (h << 6) + b);
#pragma unroll
        for (int a = 0; a < 18; a++)
            acc[a] = fmaf(x, Wds[a * 1024 + h], acc[a]);
    }
#pragma unroll
    for (int a = 0; a < 18; a++) red2[(s * 64 + b) * 18 + a] = acc[a];
    __syncthreads();

    for (int o = tid; o < 64 * 18; o += 256) {
        const int b2 = o / 18;
        const int a  = o - b2 * 18;
        float v = red2[b2 * 18 + a] + red2[(64 + b2) * 18 + a]
                + red2[(128 + b2) * 18 + a] + red2[(192 + b2) * 18 + a];
        v = (v + bd[a]) * mask[t * Bn + b2];
        out_values[(size_t)t * (Bn * An) + o] = v;
    }
}

// =====================================================================
extern "C" void kernel_launch(void* const* d_in, const int* in_sizes, int n_in,
                              void* d_out, int out_size)
{
    const float* obs   = (const float*)d_in[0];
    const float* mask  = (const float*)d_in[1];
    const float* W_enc = (const float*)d_in[2];
    const float* b_enc = (const float*)d_in[3];
    const float* W_ih  = (const float*)d_in[4];
    const float* b_ih  = (const float*)d_in[5];
    const float* W_hh  = (const float*)d_in[6];
    const float* b_hh  = (const float*)d_in[7];
    const float* W_dec = (const float*)d_in[8];
    const float* b_dec = (const float*)d_in[9];

    float* out        = (float*)d_out;
    float* out_values = out;                                   // [512][64][18]
    float* out_h      = out + (size_t)Tn * Bn * An;            // [64][1024]
    float* out_c      = out_h + (size_t)Bn * Hn;               // [64][1024]

    float* enc_ptr = nullptr;
    cudaGetSymbolAddress((void**)&enc_ptr, g_enc);

    cudaFuncSetAttribute(lstm_kernel,    cudaFuncAttributeMaxDynamicSharedMemorySize, 196608);
    cudaFuncSetAttribute(decoder_kernel, cudaFuncAttributeMaxDynamicSharedMemorySize, 92160);

    // 1) encoded = relu(obs @ W_enc^T + b_enc)          [32768,1024]
    dim3 g1(Hn / 128, Mn / 128);
    tf32_gemm<true, false, false><<<g1, 256>>>(obs, W_enc, b_enc, nullptr, enc_ptr, OBSn, Hn);

    // 2) x_gates = enc @ W_ih^T + b_ih + b_hh  -> g_xg [t][g][b]
    dim3 g2(G4n / 128, Mn / 128);
    tf32_gemm<false, true, true><<<g2, 256>>>(enc_ptr, W_ih, b_ih, b_hh, nullptr, Hn, G4n);

    // 3) persistent LSTM scan -> g_lat [t][h][b], out_h, out_c
    lstm_kernel<<<128, 256, 196608>>>(W_hh, mask, out_h, out_c, 128);

    // 4) decoder -> out_values
    decoder_kernel<<<Tn, 256, 92160>>>(W_dec, b_dec, mask, out_values);
}

// round 5
// speedup vs baseline: 2.3823x; 1.8421x over previous
#include <cuda_runtime.h>
#include <math.h>
#include <stdint.h>

#define Tn   512
#define Bn   64
#define OBSn 512
#define Hn   1024
#define An   18
#define G4n  4096
#define Mn   32768   // Tn*Bn

// ---------------- scratch (device globals; no runtime allocation) ----------------
__device__ float g_enc[(size_t)Mn * Hn];        // encoded [m][h]
__device__ float g_xg [(size_t)Tn * G4n * Bn];  // x_gates transposed [t][g][b]
__device__ float g_lat[(size_t)Tn * Hn * Bn];   // latent transposed  [t][h][b]
__device__ unsigned g_bar_count;
__device__ unsigned g_bar_gen;

__device__ __forceinline__ unsigned f2tf32(float x) {
    unsigned r;
    asm("cvt.rna.tf32.f32 %0, %1;" : "=r"(r) : "f"(x));
    return r;
}

// =====================================================================
// TF32 tensor-core GEMM, 2-stage smem double buffer.
// C[m][n] = A[m][:K] . Bm[n][:K] (+bias) (opt relu)
// Block tile 128x128, BK=16, 256 thr = 8 warps (4x2), warp tile 32x64.
// XGST mode stores transposed into g_xg as [t][n][b], m = t*64+b.
// =====================================================================
template<bool RELU, bool XGST, bool HASB2>
__global__ void __launch_bounds__(256, 2) tf32_gemm(
    const float* __restrict__ A, const float* __restrict__ Bm,
    const float* __restrict__ bias1, const float* __restrict__ bias2,
    float* __restrict__ C, int K, int N)
{
    __shared__ unsigned As[2][128][20];
    __shared__ unsigned Bs[2][128][20];
    const int tid  = threadIdx.x;
    const int wid  = tid >> 5, lane = tid & 31;
    const int wr   = wid >> 1, wc = wid & 1;
    const int gq   = lane >> 2, tg = lane & 3;
    const int bm   = blockIdx.y << 7;
    const int bn   = blockIdx.x << 7;
    const int lr   = tid >> 2;
    const int lk   = (tid & 3) << 2;

    const float* Ap = A  + (size_t)(bm + lr) * K + lk;
    const float* Bp = Bm + (size_t)(bn + lr) * K + lk;

    float4 pa0 = *(const float4*)(Ap);
    float4 pa1 = *(const float4*)(Ap + (size_t)64 * K);
    float4 pb0 = *(const float4*)(Bp);
    float4 pb1 = *(const float4*)(Bp + (size_t)64 * K);

    float acc[16][4];
#pragma unroll
    for (int t = 0; t < 16; t++)
#pragma unroll
        for (int e = 0; e < 4; e++) acc[t][e] = 0.f;

    // store tile 0 into buffer 0
    {
        uint4 u;
        u.x = f2tf32(pa0.x); u.y = f2tf32(pa0.y); u.z = f2tf32(pa0.z); u.w = f2tf32(pa0.w);
        *(uint4*)&As[0][lr][lk] = u;
        u.x = f2tf32(pa1.x); u.y = f2tf32(pa1.y); u.z = f2tf32(pa1.z); u.w = f2tf32(pa1.w);
        *(uint4*)&As[0][lr + 64][lk] = u;
        u.x = f2tf32(pb0.x); u.y = f2tf32(pb0.y); u.z = f2tf32(pb0.z); u.w = f2tf32(pb0.w);
        *(uint4*)&Bs[0][lr][lk] = u;
        u.x = f2tf32(pb1.x); u.y = f2tf32(pb1.y); u.z = f2tf32(pb1.z); u.w = f2tf32(pb1.w);
        *(uint4*)&Bs[0][lr + 64][lk] = u;
    }
    __syncthreads();

    int p = 0;
    for (int k0 = 0; k0 < K; k0 += 16) {
        const bool more = (k0 + 16) < K;
        if (more) {
            pa0 = *(const float4*)(Ap + k0 + 16);
            pa1 = *(const float4*)(Ap + (size_t)64 * K + k0 + 16);
            pb0 = *(const float4*)(Bp + k0 + 16);
            pb1 = *(const float4*)(Bp + (size_t)64 * K + k0 + 16);
        }

#pragma unroll
        for (int ks = 0; ks < 2; ks++) {
            const int kf = ks << 3;
            unsigned af[2][4], bf[8][2];
#pragma unroll
            for (int i = 0; i < 2; i++) {
                const int mr = (wr << 5) + (i << 4) + gq;
                af[i][0] = As[p][mr][kf + tg];
                af[i][1] = As[p][mr + 8][kf + tg];
                af[i][2] = As[p][mr][kf + tg + 4];
                af[i][3] = As[p][mr + 8][kf + tg + 4];
            }
#pragma unroll
            for (int j = 0; j < 8; j++) {
                const int nn = (wc << 6) + (j << 3) + gq;
                bf[j][0] = Bs[p][nn][kf + tg];
                bf[j][1] = Bs[p][nn][kf + tg + 4];
            }
#pragma unroll
            for (int i = 0; i < 2; i++)
#pragma unroll
                for (int j = 0; j < 8; j++) {
                    float* c = acc[i * 8 + j];
                    asm volatile(
                        "mma.sync.aligned.m16n8k8.row.col.f32.tf32.tf32.f32 "
                        "{%0,%1,%2,%3}, {%4,%5,%6,%7}, {%8,%9}, {%0,%1,%2,%3};"
                        : "+f"(c[0]), "+f"(c[1]), "+f"(c[2]), "+f"(c[3])
                        : "r"(af[i][0]), "r"(af[i][1]), "r"(af[i][2]), "r"(af[i][3]),
                          "r"(bf[j][0]), "r"(bf[j][1]));
                }
        }

        if (more) {
            const int q = p ^ 1;
            uint4 u;
            u.x = f2tf32(pa0.x); u.y = f2tf32(pa0.y); u.z = f2tf32(pa0.z); u.w = f2tf32(pa0.w);
            *(uint4*)&As[q][lr][lk] = u;
            u.x = f2tf32(pa1.x); u.y = f2tf32(pa1.y); u.z = f2tf32(pa1.z); u.w = f2tf32(pa1.w);
            *(uint4*)&As[q][lr + 64][lk] = u;
            u.x = f2tf32(pb0.x); u.y = f2tf32(pb0.y); u.z = f2tf32(pb0.z); u.w = f2tf32(pb0.w);
            *(uint4*)&Bs[q][lr][lk] = u;
            u.x = f2tf32(pb1.x); u.y = f2tf32(pb1.y); u.z = f2tf32(pb1.z); u.w = f2tf32(pb1.w);
            *(uint4*)&Bs[q][lr + 64][lk] = u;
            __syncthreads();
            p = q;
        }
    }

    // ---- epilogue ----
#pragma unroll
    for (int i = 0; i < 2; i++) {
#pragma unroll
        for (int j = 0; j < 8; j++) {
            const int r0 = bm + (wr << 5) + (i << 4) + gq;
            const int cb = bn + (wc << 6) + (j << 3) + (tg << 1);
            float bv0 = bias1[cb]     + (HASB2 ? bias2[cb]     : 0.f);
            float bv1 = bias1[cb + 1] + (HASB2 ? bias2[cb + 1] : 0.f);
            const float* c = acc[i * 8 + j];
            float v00 = c[0] + bv0, v01 = c[1] + bv1;
            float v10 = c[2] + bv0, v11 = c[3] + bv1;
            if (RELU) {
                v00 = fmaxf(v00, 0.f); v01 = fmaxf(v01, 0.f);
                v10 = fmaxf(v10, 0.f); v11 = fmaxf(v11, 0.f);
            }
            if (XGST) {
                const int t0 = r0 >> 6, b0 = r0 & 63;
                const int t1 = (r0 + 8) >> 6, b1 = (r0 + 8) & 63;
                g_xg[((size_t)t0 * G4n + cb)     * Bn + b0] = v00;
                g_xg[((size_t)t0 * G4n + cb + 1) * Bn + b0] = v01;
                g_xg[((size_t)t1 * G4n + cb)     * Bn + b1] = v10;
                g_xg[((size_t)t1 * G4n + cb + 1) * Bn + b1] = v11;
            } else {
                *(float2*)(C + (size_t)r0 * N + cb)       = make_float2(v00, v01);
                *(float2*)(C + (size_t)(r0 + 8) * N + cb) = make_float2(v10, v11);
            }
        }
    }
}

// =====================================================================
// Persistent LSTM scan with TF32 tensor cores.
// 128 blocks x 256 thr. Block owns 8 hidden units -> 32 gate rows.
// Output tile [32 rows][64 batch] = 2x8 m16n8 mma tiles.
// W_hh tf32 in smem Ws[32][1028] (pitch%32==4 -> conflict-free A frags).
// h staged per step in 4 chunks of [256k][64b] into hs[256][72]
// (pitch%32==8 -> conflict-free B frags). Warps split k 8-ways; partials
// reduced via smem aliased onto hs.
// =====================================================================
#define WS_PITCH 1028
#define HS_PITCH 72
#define RED_PITCH 66

__device__ __forceinline__ float sigf(float x) { return 1.f / (1.f + __expf(-x)); }

__global__ void __launch_bounds__(256, 1) lstm_kernel(
    const float* __restrict__ W_hh, const float* __restrict__ mask,
    float* __restrict__ out_h, float* __restrict__ out_c, int nblk)
{
    extern __shared__ unsigned smu[];
    unsigned* Ws = smu;                       // [32][1028] tf32
    unsigned* hs = smu + 32 * WS_PITCH;       // [256][72] tf32, aliased as red
    float*   red = (float*)hs;                // [8][32][66] fp32

    const int tid  = threadIdx.x;
    const int wid  = tid >> 5, lane = tid & 31;
    const int gq   = lane >> 2, tg = lane & 3;
    const int j0   = blockIdx.x << 3;

    // stage W_hh rows (r = q*8 + jj  <->  global row q*1024 + j0 + jj), tf32
    for (int i = tid; i < 32 * 256; i += 256) {
        const int r  = i >> 8;
        const int kq = (i & 255) << 2;
        const int grow = ((r >> 3) << 10) + j0 + (r & 7);
        const float4 w = *(const float4*)(W_hh + (size_t)grow * Hn + kq);
        uint4 u;
        u.x = f2tf32(w.x); u.y = f2tf32(w.y); u.z = f2tf32(w.z); u.w = f2tf32(w.w);
        *(uint4*)&Ws[r * WS_PITCH + kq] = u;
    }

    float c0r = 0.f, c1r = 0.f;
    unsigned gen = 0;
    if (tid == 0) gen = *(volatile unsigned*)&g_bar_gen;
    __syncthreads();

    for (int t = 0; t < Tn; t++) {
        if (t > 0) {
            float acc[16][4];
#pragma unroll
            for (int q = 0; q < 16; q++)
#pragma unroll
                for (int e = 0; e < 4; e++) acc[q][e] = 0.f;

            const float* Hp = g_lat + (size_t)(t - 1) * (Hn * Bn);

            for (int cc = 0; cc < 4; cc++) {
                __syncthreads();   // hs free (prev chunk consumed / prev-step reduce done)
                // stage chunk cc: h[cc*256 + k][b] -> hs[k][b] (tf32)
#pragma unroll
                for (int ii = 0; ii < 16; ii++) {
                    const int e4 = tid + (ii << 8);       // 0..4095 float4s
                    const int k  = e4 >> 4;               // 0..255
                    const int b  = (e4 & 15) << 2;        // 0..60
                    const float4 v = __ldcg((const float4*)(Hp + (((size_t)(cc << 8) + k) << 6) + b));
                    uint4 u;
                    u.x = f2tf32(v.x); u.y = f2tf32(v.y); u.z = f2tf32(v.z); u.w = f2tf32(v.w);
                    *(uint4*)&hs[k * HS_PITCH + b] = u;
                }
                __syncthreads();

                // mma: this warp's k-slice [wid*32, wid*32+32) of the chunk
#pragma unroll
                for (int s = 0; s < 4; s++) {
                    const int kl = (wid << 5) + (s << 3);   // local k in chunk
                    const int kg = (cc << 8) + kl;          // global k
                    unsigned af[2][4], bf[8][2];
#pragma unroll
                    for (int i = 0; i < 2; i++) {
                        const int r = (i << 4) + gq;
                        af[i][0] = Ws[r * WS_PITCH + kg + tg];
                        af[i][1] = Ws[(r + 8) * WS_PITCH + kg + tg];
                        af[i][2] = Ws[r * WS_PITCH + kg + tg + 4];
                        af[i][3] = Ws[(r + 8) * WS_PITCH + kg + tg + 4];
                    }
#pragma unroll
                    for (int j = 0; j < 8; j++) {
                        bf[j][0] = hs[(kl + tg) * HS_PITCH + (j << 3) + gq];
                        bf[j][1] = hs[(kl + tg + 4) * HS_PITCH + (j << 3) + gq];
                    }
#pragma unroll
                    for (int i = 0; i < 2; i++)
#pragma unroll
                        for (int j = 0; j < 8; j++) {
                            float* c = acc[i * 8 + j];
                            asm volatile(
                                "mma.sync.aligned.m16n8k8.row.col.f32.tf32.tf32.f32 "
                                "{%0,%1,%2,%3}, {%4,%5,%6,%7}, {%8,%9}, {%0,%1,%2,%3};"
                                : "+f"(c[0]), "+f"(c[1]), "+f"(c[2]), "+f"(c[3])
                                : "r"(af[i][0]), "r"(af[i][1]), "r"(af[i][2]), "r"(af[i][3]),
                                  "r"(bf[j][0]), "r"(bf[j][1]));
                        }
                }
            }
            __syncthreads();   // all mma done; hs reusable as red

            // publish split-K partials: red[wid][r][b]
#pragma unroll
            for (int i = 0; i < 2; i++)
#pragma unroll
                for (int j = 0; j < 8; j++) {
                    const float* c = acc[i * 8 + j];
                    const int r = (i << 4) + gq;
                    const int b = (j << 3) + (tg << 1);
                    *(float2*)&red[((wid << 5) + r) * RED_PITCH + b]     = make_float2(c[0], c[1]);
                    *(float2*)&red[((wid << 5) + r + 8) * RED_PITCH + b] = make_float2(c[2], c[3]);
                }
            __syncthreads();

            // reduce + activations
#pragma unroll
            for (int pp = 0; pp < 2; pp++) {
                const int p  = tid + (pp << 8);
                const int jj = p >> 6;
                const int b  = p & 63;
                float gate[4];
#pragma unroll
                for (int q = 0; q < 4; q++) {
                    const int r = (q << 3) + jj;
                    float s = g_xg[((size_t)t * G4n + (q << 10) + j0 + jj) * Bn + b];
#pragma unroll
                    for (int w8 = 0; w8 < 8; w8++)
                        s += red[((w8 << 5) + r) * RED_PITCH + b];
                    gate[q] = s;
                }
                const float cprev = pp ? c1r : c0r;
                float cn = sigf(gate[1]) * cprev + sigf(gate[0]) * tanhf(gate[2]);
                float hn = sigf(gate[3]) * tanhf(cn);
                const float m = mask[t * Bn + b];
                hn *= m; cn *= m;
                if (pp) c1r = cn; else c0r = cn;
                g_lat[(size_t)t * (Hn * Bn) + ((size_t)(j0 + jj) << 6) + b] = hn;
                if (t == Tn - 1) {
                    out_h[b * Hn + j0 + jj] = hn;
                    out_c[b * Hn + j0 + jj] = cn;
                }
            }
        } else {
            // t == 0: h0 = 0 -> gates = x_gates only
#pragma unroll
            for (int pp = 0; pp < 2; pp++) {
                const int p  = tid + (pp << 8);
                const int jj = p >> 6;
                const int b  = p & 63;
                float gate[4];
#pragma unroll
                for (int q = 0; q < 4; q++)
                    gate[q] = g_xg[((size_t)t * G4n + (q << 10) + j0 + jj) * Bn + b];
                const float cprev = pp ? c1r : c0r;
                float cn = sigf(gate[1]) * cprev + sigf(gate[0]) * tanhf(gate[2]);
                float hn = sigf(gate[3]) * tanhf(cn);
                const float m = mask[t * Bn + b];
                hn *= m; cn *= m;
                if (pp) c1r = cn; else c0r = cn;
                g_lat[(size_t)t * (Hn * Bn) + ((size_t)(j0 + jj) << 6) + b] = hn;
            }
        }

        // ---- grid barrier ----
        __threadfence();
        __syncthreads();
        if (tid == 0) {
            const unsigned arr = atomicAdd(&g_bar_count, 1);
            if (arr == (unsigned)(nblk - 1)) {
                atomicExch(&g_bar_count, 0);
                __threadfence();
                atomicAdd(&g_bar_gen, 1);
            } else {
                while (*(volatile unsigned*)&g_bar_gen == gen) { }
            }
            gen++;
            __threadfence();
        }
        __syncthreads();
    }
}

// =====================================================================
// Decoder (unchanged)
// =====================================================================
__global__ void __launch_bounds__(256, 1) decoder_kernel(
    const float* __restrict__ Wd, const float* __restrict__ bd,
    const float* __restrict__ mask, float* __restrict__ out_values)
{
    extern __shared__ float dsm[];
    float* Wds  = dsm;               // [18][1024]
    float* red2 = dsm + 18 * 1024;   // [4][64][18]
    const int t = blockIdx.x;
    const int tid = threadIdx.x;

    for (int i = tid; i < (18 * 1024) / 4; i += 256)
        ((float4*)Wds)[i] = ((const float4*)Wd)[i];
    __syncthreads();

    const int s = tid >> 6;
    const int b = tid & 63;
    float acc[18];
#pragma unroll
    for (int a = 0; a < 18; a++) acc[a] = 0.f;

    const float* L = g_lat + (size_t)t * (Hn * Bn);
    const int hend = (s + 1) << 8;
    for (int h = s << 8; h < hend; h++) {
        const float x = __ldcg(L + (h << 6) + b);
#pragma unroll
        for (int a = 0; a < 18; a++)
            acc[a] = fmaf(x, Wds[a * 1024 + h], acc[a]);
    }
#pragma unroll
    for (int a = 0; a < 18; a++) red2[(s * 64 + b) * 18 + a] = acc[a];
    __syncthreads();

    for (int o = tid; o < 64 * 18; o += 256) {
        const int b2 = o / 18;
        const int a  = o - b2 * 18;
        float v = red2[b2 * 18 + a] + red2[(64 + b2) * 18 + a]
                + red2[(128 + b2) * 18 + a] + red2[(192 + b2) * 18 + a];
        v = (v + bd[a]) * mask[t * Bn + b2];
        out_values[(size_t)t * (Bn * An) + o] = v;
    }
}

// =====================================================================
extern "C" void kernel_launch(void* const* d_in, const int* in_sizes, int n_in,
                              void* d_out, int out_size)
{
    const float* obs   = (const float*)d_in[0];
    const float* mask  = (const float*)d_in[1];
    const float* W_enc = (const float*)d_in[2];
    const float* b_enc = (const float*)d_in[3];
    const float* W_ih  = (const float*)d_in[4];
    const float* b_ih  = (const float*)d_in[5];
    const float* W_hh  = (const float*)d_in[6];
    const float* b_hh  = (const float*)d_in[7];
    const float* W_dec = (const float*)d_in[8];
    const float* b_dec = (const float*)d_in[9];

    float* out        = (float*)d_out;
    float* out_values = out;                                   // [512][64][18]
    float* out_h      = out + (size_t)Tn * Bn * An;            // [64][1024]
    float* out_c      = out_h + (size_t)Bn * Hn;               // [64][1024]

    float* enc_ptr = nullptr;
    cudaGetSymbolAddress((void**)&enc_ptr, g_enc);

    const int lstm_smem = (32 * WS_PITCH + 256 * HS_PITCH) * 4;   // 205312 B
    cudaFuncSetAttribute(lstm_kernel,    cudaFuncAttributeMaxDynamicSharedMemorySize, lstm_smem);
    cudaFuncSetAttribute(decoder_kernel, cudaFuncAttributeMaxDynamicSharedMemorySize, 92160);

    // 1) encoded = relu(obs @ W_enc^T + b_enc)          [32768,1024]
    dim3 g1(Hn / 128, Mn / 128);
    tf32_gemm<true, false, false><<<g1, 256>>>(obs, W_enc, b_enc, nullptr, enc_ptr, OBSn, Hn);

    // 2) x_gates = enc @ W_ih^T + b_ih + b_hh  -> g_xg [t][g][b]
    dim3 g2(G4n / 128, Mn / 128);
    tf32_gemm<false, true, true><<<g2, 256>>>(enc_ptr, W_ih, b_ih, b_hh, nullptr, Hn, G4n);

    // 3) persistent LSTM scan -> g_lat [t][h][b], out_h, out_c
    lstm_kernel<<<128, 256, lstm_smem>>>(W_hh, mask, out_h, out_c, 128);

    // 4) decoder -> out_values
    decoder_kernel<<<Tn, 256, 92160>>>(W_dec, b_dec, mask, out_values);
}